// round 12
// baseline (speedup 1.0000x reference)
#include <cuda_runtime.h>
#include <cuda_bf16.h>

// R9: coefficients move to the CONSTANT BANK (uniform-register path).
//  setup kernel decodes E -> __device__ gCoef[69]  ->  cudaMemcpyToSymbolAsync
//  -> __constant__ cC[69]. Main kernel reads cC with unroll-constant indices:
//  ptxas lowers these to LDCU/UR (uniform regs, separate file), freeing ~65
//  vector registers per thread. That breaks the regs=117 -> 2 CTA/SM cap that
//  has pinned every round at ~10.8us: now 3 CTAs/SM, 24 warps.
// Layout of cC: [0:5) c1, [5:20) c2, [20:55) c3 (lex i<=j<=k),
//               [55:60) ctc, [60:65) cts, [65] w0, [66] w1, [67] e0, [68] e1.

#define NBLK 444
#define NTHR 256
#define TOTT (NBLK * NTHR)   // 113664 threads = row-pairs per iteration

__constant__ float cC[69];
__device__ float gCoef[69];

__global__ void ExternalForcesSI_setup_kernel(const int* __restrict__ E,
                                              const float* __restrict__ layer,
                                              const float* __restrict__ omegas,
                                              const float* __restrict__ ef) {
    int tx = threadIdx.x;
    if (tx < 55) {
        int vars[3];
        int nv = 0;
        for (int j = 0; j < 5; j++) {
            int c = E[tx * 5 + j];
            for (int r = 0; r < c; r++) vars[nv++] = j;   // ascending
        }
        float coef = layer[tx];
        if (nv == 1) {
            gCoef[vars[0]] = coef;
        } else if (nv == 2) {
            // upper-tri pair index, lex order
            int q = 0;
            for (int i = 0; i < 5; i++)
                for (int j = i; j < 5; j++) {
                    if (i == vars[0] && j == vars[1]) gCoef[5 + q];
                    q++;
                }
            q = 0;
            for (int i = 0; i < 5 && nv == 2; i++)
                for (int j = i; j < 5; j++) {
                    if (i == vars[0] && j == vars[1]) { gCoef[5 + q] = coef; }
                    q++;
                }
        } else {
            int q = 0;
            for (int i = 0; i < 5; i++)
                for (int j = i; j < 5; j++)
                    for (int k = j; k < 5; k++) {
                        if (i == vars[0] && j == vars[1] && k == vars[2])
                            gCoef[20 + q] = coef;
                        q++;
                    }
        }
    } else if (tx < 65) {
        gCoef[tx] = layer[tx];          // ctc (55..59), cts (60..64)
    } else if (tx == 65) {
        gCoef[65] = omegas[0];
    } else if (tx == 66) {
        gCoef[66] = omegas[1];
    } else if (tx == 67) {
        gCoef[67] = ef[0];
    } else if (tx == 68) {
        gCoef[68] = ef[1];
    }
}

struct Pair { float a[5]; float b[5]; };

__device__ __forceinline__ void load_pair(const float4* __restrict__ xp,
                                          const float2* __restrict__ tp,
                                          int off, Pair& P) {
    float4 x0 = xp[2 * off];
    float4 x1 = xp[2 * off + 1];
    float2 tt = tp[off];
    P.a[0] = x0.x; P.a[1] = x0.y; P.a[2] = x0.z; P.a[3] = x0.w; P.a[4] = tt.x;
    P.b[0] = x1.x; P.b[1] = x1.y; P.b[2] = x1.z; P.b[3] = x1.w; P.b[4] = tt.y;
}

// Per-row polynomial + trig epilogue; all coefficients from the constant bank.
__device__ __forceinline__ float row_eval(const float* v,
                                          const float* C, const float* S) {
    float part[5];
    int q2 = 0, q3 = 0;
    #pragma unroll
    for (int i = 0; i < 5; i++) {
        float ui = cC[i];
        #pragma unroll
        for (int j = i; j < 5; j++) {
            float tij = cC[5 + q2]; q2++;
            #pragma unroll
            for (int k = j; k < 5; k++) {
                tij = fmaf(v[k], cC[20 + q3], tij); q3++;
            }
            ui = fmaf(v[j], tij, ui);
        }
        part[i] = v[i] * ui;
    }
    float a01 = fmaf(cC[55], C[0], cC[56] * C[1]);
    float a23 = fmaf(cC[57], C[2], cC[58] * C[3]);
    float b01 = fmaf(cC[60], S[0], cC[61] * S[1]);
    float b23 = fmaf(cC[62], S[2], cC[63] * S[3]);
    float a4  = fmaf(cC[59], C[4], cC[64] * S[4]);
    return (((part[0] + part[1]) + (part[2] + part[3])) + part[4])
           + (((a01 + a23) + (b01 + b23)) + a4);
}

template<int NITER>
__global__ __launch_bounds__(NTHR, 3)
void ExternalForcesSI_main_kernel(const float4* __restrict__ x,
                                  const float2* __restrict__ t2,
                                  float4* __restrict__ out,
                                  int npairs, int iters_rt) {
    const int tid = blockIdx.x * NTHR + threadIdx.x;
    const int pm1 = npairs - 1;
    const int iters = (NITER > 0) ? NITER : iters_rt;

    const float w0 = cC[65];
    const float w1 = cC[66];
    const float e0 = cC[67];
    const float e1 = cC[68];

    const float4* __restrict__ xp = x + 2 * tid;
    const float2* __restrict__ tp = t2 + tid;
    float4* __restrict__ op = out + tid;

    Pair buf[2];
    if (NITER > 0) load_pair(xp, tp, 0, buf[0]);
    else           load_pair(xp, tp, min(tid, pm1) - tid, buf[0]);

    #pragma unroll
    for (int it = 0; it < iters; it++) {
        const int cur = it & 1;
        const int nxt = cur ^ 1;

        // ---- prefetch next pair FIRST ----
        if (it + 1 < iters) {
            if (NITER > 0 && it + 2 < iters) {
                load_pair(xp, tp, (it + 1) * TOTT, buf[nxt]);   // in-bounds
            } else {
                int pc = min(tid + (it + 1) * TOTT, pm1) - tid;
                load_pair(xp, tp, pc, buf[nxt]);
            }
        }

        const float* va = buf[cur].a;
        const float* vb = buf[cur].b;

        // ---- trig: issue all 20 MUFUs early ----
        float Ca[5], Sa[5], Cb[5], Sb[5];
        #pragma unroll
        for (int j = 0; j < 5; j++) {
            Ca[j] = __cosf(w0 * va[j]);
            Sa[j] = __sinf(w1 * va[j]);
            Cb[j] = __cosf(w0 * vb[j]);
            Sb[j] = __sinf(w1 * vb[j]);
        }

        float sA = row_eval(va, Ca, Sa);
        float sB = row_eval(vb, Cb, Sb);

        float4 res = make_float4(sA * e0, sA * e1, sB * e0, sB * e1);
        if (NITER > 0 && it + 1 < iters) {
            op[it * TOTT] = res;                      // provably in-bounds
        } else {
            if (tid + it * TOTT < npairs) op[it * TOTT] = res;
        }
    }
}

extern "C" void kernel_launch(void* const* d_in, const int* in_sizes, int n_in,
                              void* d_out, int out_size) {
    // metadata order: x, t, layer, omegas, ext_filter, E
    const float4* x      = (const float4*)d_in[0];
    const float2* t2     = (const float2*)d_in[1];
    const float*  layer  = (const float*)d_in[2];
    const float*  omegas = (const float*)d_in[3];
    const float*  ef     = (const float*)d_in[4];
    const int*    E      = (const int*)d_in[5];
    float4* out = (float4*)d_out;

    const int n = in_sizes[1];        // N_DATA (element count of t), even
    const int npairs = n >> 1;        // 500000
    const int iters = (npairs + TOTT - 1) / TOTT;

    // 1) decode E into gCoef on-device
    ExternalForcesSI_setup_kernel<<<1, 96>>>(E, layer, omegas, ef);

    // 2) gCoef -> constant bank (device-to-device memcpy node, capturable)
    void* src = nullptr;
    cudaGetSymbolAddress(&src, gCoef);
    cudaMemcpyToSymbolAsync(cC, src, 69 * sizeof(float), 0,
                            cudaMemcpyDeviceToDevice, 0);

    // 3) main kernel, 3 CTAs/SM
    if (iters == 5 && (iters - 1) * TOTT <= npairs) {
        ExternalForcesSI_main_kernel<5><<<NBLK, NTHR>>>(x, t2, out, npairs, iters);
    } else {
        ExternalForcesSI_main_kernel<0><<<NBLK, NTHR>>>(x, t2, out, npairs, iters);
    }
}

// round 13
// speedup vs baseline: 1.4625x; 1.4625x over previous
#include <cuda_runtime.h>
#include <cuda_bf16.h>

// R10: single kernel (R9's 2-node constant-bank tax removed). Coefficients
// live in SHARED, decoded per block; each coefficient is ONE broadcast LDS
// feeding BOTH rows' FMAs (interleaved two-row Horner), so no per-thread
// vector registers hold the 65 warp-uniform values. Trig is accumulated
// immediately (no C/S arrays) to keep live registers small. Target: <=85
// regs -> 6 CTAs of 128 on each SM (24 warps) with no spills.
// sC layout: [0:5) c1, [5:20) c2 lex, [20:55) c3 lex, [55:60) ctc, [60:65) cts.

#define NBLK 888             // 148 SMs * 6 CTAs
#define NTHR 128
#define TOTT (NBLK * NTHR)   // 113664 row-pairs per iteration

struct Pair { float a[5]; float b[5]; };

__device__ __forceinline__ void load_pair(const float4* __restrict__ xp,
                                          const float2* __restrict__ tp,
                                          int off, Pair& P) {
    float4 x0 = xp[2 * off];
    float4 x1 = xp[2 * off + 1];
    float2 tt = tp[off];
    P.a[0] = x0.x; P.a[1] = x0.y; P.a[2] = x0.z; P.a[3] = x0.w; P.a[4] = tt.x;
    P.b[0] = x1.x; P.b[1] = x1.y; P.b[2] = x1.z; P.b[3] = x1.w; P.b[4] = tt.y;
}

template<int NITER>
__global__ __launch_bounds__(NTHR, 6)
void ExternalForcesSI_main_kernel(const float4* __restrict__ x,
                                  const float2* __restrict__ t2,
                                  const float* __restrict__ layer,
                                  const float* __restrict__ omegas,
                                  const float* __restrict__ ef,
                                  const int*   __restrict__ E,
                                  float4* __restrict__ out,
                                  int npairs, int iters_rt) {
    __shared__ float sC[65];

    // ---- block-local decode of E -> canonical lex slots in shared ----
    const int tx = threadIdx.x;
    if (tx < 55) {
        int vars[3];
        int nv = 0;
        #pragma unroll
        for (int j = 0; j < 5; j++) {
            int c = E[tx * 5 + j];
            for (int r = 0; r < c; r++) vars[nv++] = j;   // ascending
        }
        float coef = layer[tx];
        if (nv == 1) {
            sC[vars[0]] = coef;
        } else if (nv == 2) {
            int q = 0;
            for (int i = 0; i < 5; i++)
                for (int j = i; j < 5; j++) {
                    if (i == vars[0] && j == vars[1]) sC[5 + q] = coef;
                    q++;
                }
        } else {
            int q = 0;
            for (int i = 0; i < 5; i++)
                for (int j = i; j < 5; j++)
                    for (int k = j; k < 5; k++) {
                        if (i == vars[0] && j == vars[1] && k == vars[2])
                            sC[20 + q] = coef;
                        q++;
                    }
        }
    } else if (tx >= 64 && tx < 74) {
        sC[55 + (tx - 64)] = layer[55 + (tx - 64)];   // ctc, cts
    }
    __syncthreads();

    const float w0 = omegas[0];
    const float w1 = omegas[1];
    const float e0 = ef[0];
    const float e1 = ef[1];

    const int tid = blockIdx.x * NTHR + tx;
    const int pm1 = npairs - 1;
    const int iters = (NITER > 0) ? NITER : iters_rt;

    const float4* __restrict__ xp = x + 2 * tid;
    const float2* __restrict__ tp = t2 + tid;
    float4* __restrict__ op = out + tid;

    // ---- parity double-buffer prologue ----
    Pair buf[2];
    if (NITER > 0) load_pair(xp, tp, 0, buf[0]);
    else           load_pair(xp, tp, min(tid, pm1) - tid, buf[0]);

    #pragma unroll
    for (int it = 0; it < iters; it++) {
        const int cur = it & 1;
        const int nxt = cur ^ 1;

        // ---- prefetch next pair FIRST (LDGs fly during compute) ----
        if (it + 1 < iters) {
            if (NITER > 0 && it + 2 < iters) {
                load_pair(xp, tp, (it + 1) * TOTT, buf[nxt]);   // in-bounds
            } else {
                int pc = min(tid + (it + 1) * TOTT, pm1) - tid;
                load_pair(xp, tp, pc, buf[nxt]);
            }
        }

        const float* va = buf[cur].a;
        const float* vb = buf[cur].b;

        // ---- trig: folded accumulation, two short chains per row ----
        float trigA, trigB;
        {
            float ca = 0.f, sa = 0.f, cb = 0.f, sb = 0.f;
            #pragma unroll
            for (int j = 0; j < 5; j++) {
                float cc = sC[55 + j];       // one LDS each, both rows
                float ss = sC[60 + j];
                ca = fmaf(cc, __cosf(w0 * va[j]), ca);
                sa = fmaf(ss, __sinf(w1 * va[j]), sa);
                cb = fmaf(cc, __cosf(w0 * vb[j]), cb);
                sb = fmaf(ss, __sinf(w1 * vb[j]), sb);
            }
            trigA = ca + sa;
            trigB = cb + sb;
        }

        // ---- interleaved two-row Horner: each sC load feeds both rows ----
        float sA, sB;
        {
            float pA[5], pB[5];
            int q2 = 0, q3 = 0;
            #pragma unroll
            for (int i = 0; i < 5; i++) {
                float uiA = sC[i], uiB = uiA;
                #pragma unroll
                for (int j = i; j < 5; j++) {
                    float c2v = sC[5 + q2]; q2++;
                    float tA = c2v, tB = c2v;
                    #pragma unroll
                    for (int k = j; k < 5; k++) {
                        float c3v = sC[20 + q3]; q3++;
                        tA = fmaf(va[k], c3v, tA);
                        tB = fmaf(vb[k], c3v, tB);
                    }
                    uiA = fmaf(va[j], tA, uiA);
                    uiB = fmaf(vb[j], tB, uiB);
                }
                pA[i] = va[i] * uiA;
                pB[i] = vb[i] * uiB;
            }
            sA = (((pA[0] + pA[1]) + (pA[2] + pA[3])) + pA[4]) + trigA;
            sB = (((pB[0] + pB[1]) + (pB[2] + pB[3])) + pB[4]) + trigB;
        }

        // ---- one STG.128 per pair; unpredicated on clean iterations ----
        float4 res = make_float4(sA * e0, sA * e1, sB * e0, sB * e1);
        if (NITER > 0 && it + 1 < iters) {
            op[it * TOTT] = res;                      // provably in-bounds
        } else {
            if (tid + it * TOTT < npairs) op[it * TOTT] = res;
        }
    }
}

extern "C" void kernel_launch(void* const* d_in, const int* in_sizes, int n_in,
                              void* d_out, int out_size) {
    // metadata order: x, t, layer, omegas, ext_filter, E
    const float4* x      = (const float4*)d_in[0];
    const float2* t2     = (const float2*)d_in[1];
    const float*  layer  = (const float*)d_in[2];
    const float*  omegas = (const float*)d_in[3];
    const float*  ef     = (const float*)d_in[4];
    const int*    E      = (const int*)d_in[5];
    float4* out = (float4*)d_out;

    const int n = in_sizes[1];        // N_DATA (element count of t), even
    const int npairs = n >> 1;        // 500000
    const int iters = (npairs + TOTT - 1) / TOTT;   // 5 for N=1M

    // Guard-specialized fast path valid when iterations 0..iters-2 are
    // provably in-bounds for every thread: (iters-1)*TOTT <= npairs.
    if (iters == 5 && (iters - 1) * TOTT <= npairs) {
        ExternalForcesSI_main_kernel<5><<<NBLK, NTHR>>>(
            x, t2, layer, omegas, ef, E, out, npairs, iters);
    } else {
        ExternalForcesSI_main_kernel<0><<<NBLK, NTHR>>>(
            x, t2, layer, omegas, ef, E, out, npairs, iters);
    }
}